// round 5
// baseline (speedup 1.0000x reference)
#include <cuda_runtime.h>
#include <cuda_bf16.h>
#include <cstdint>

// ---------------------------------------------------------------------------
// Problem constants
// ---------------------------------------------------------------------------
#define NFEAT   128
#define EFEAT   16
#define DDIM    300
#define DDIM2   600
#define LAYERS  3
#define NGRAPH  256
#define OUTF    128
#define BN_EPS  1e-5f

#define MAX_NODES 50000
#define MAX_EDGES 800000

// ---------------------------------------------------------------------------
// Scratch (device globals; no allocations allowed)
// ---------------------------------------------------------------------------
__device__ float g_hn [MAX_NODES * DDIM];
__device__ float g_acc[MAX_NODES * DDIM];
__device__ float g_y1 [MAX_NODES * DDIM2];
__device__ float g_y2 [MAX_NODES * DDIM];
__device__ float g_sum  [DDIM2];     // zero at graph entry; finalize re-zeros
__device__ float g_sumsq[DDIM2];
__device__ float g_scale[DDIM2];
__device__ float g_shift[DDIM2];
__device__ float g_hg [NGRAPH * DDIM];

// ---------------------------------------------------------------------------
// bf16x3 split GEMM:  C = f(A) @ B + bias   (f = optional per-K BN + relu)
// Each fp32 operand -> hi/lo bf16 planes in smem (split once at tile load).
// acc += al*bh + ah*bl + ah*bh  via mma.sync.m16n8k16.bf16 (3 MMAs / frag).
// Block tile 128x64x32, 8 warps (4x2), warp tile 32x32.
// A planes: uint32 [128][20]  (16 kpairs + 4 pad)  -> frag LDS conflict-free
// B planes: uint32 [16][72]   (64 n + 8 pad)       -> frag LDS conflict-free
// ---------------------------------------------------------------------------
#define TBM 128
#define TBN 64
#define TBK 32
#define AP_STR 20
#define BP_STR 72

__device__ __forceinline__ uint32_t pack2(__nv_bfloat16 a, __nv_bfloat16 b)
{
    return ((uint32_t)__bfloat16_as_ushort(b) << 16) | __bfloat16_as_ushort(a);
}

// split pair (x0 = even k, x1 = odd k) into packed hi / lo bf16x2 words
__device__ __forceinline__ void split2(float x0, float x1,
                                       uint32_t& hi, uint32_t& lo)
{
    __nv_bfloat16 h0 = __float2bfloat16(x0);
    __nv_bfloat16 h1 = __float2bfloat16(x1);
    float r0 = x0 - __bfloat162float(h0);
    float r1 = x1 - __bfloat162float(h1);
    hi = pack2(h0, h1);
    lo = pack2(__float2bfloat16(r0), __float2bfloat16(r1));
}

__device__ __forceinline__ void mma_bf16(float acc[4], const uint32_t a[4],
                                         const uint32_t b[2])
{
    asm volatile(
        "mma.sync.aligned.m16n8k16.row.col.f32.bf16.bf16.f32 "
        "{%0,%1,%2,%3}, {%4,%5,%6,%7}, {%8,%9}, {%0,%1,%2,%3};"
        : "+f"(acc[0]), "+f"(acc[1]), "+f"(acc[2]), "+f"(acc[3])
        : "r"(a[0]), "r"(a[1]), "r"(a[2]), "r"(a[3]), "r"(b[0]), "r"(b[1]));
}

__global__ __launch_bounds__(256)
void gemm_bf16x3_kernel(const float* __restrict__ A, const float* __restrict__ B,
                        const float* __restrict__ bias,
                        const float* __restrict__ scaleA,
                        const float* __restrict__ shiftA, int reluA,
                        float* __restrict__ C, float* __restrict__ C2,
                        int M, int N, int K)
{
    __shared__ __align__(16) uint32_t Ah[TBM * AP_STR];
    __shared__ __align__(16) uint32_t Al[TBM * AP_STR];
    __shared__ __align__(16) uint32_t Bh[16 * BP_STR];
    __shared__ __align__(16) uint32_t Bl[16 * BP_STR];

    const int tid  = threadIdx.x;
    const int warp = tid >> 5;
    const int lane = tid & 31;
    const int wm = warp >> 1;        // 0..3
    const int wn = warp & 1;         // 0..1
    const int r  = lane >> 2;        // 0..7
    const int c  = lane & 3;         // 0..3
    const int bm = blockIdx.y * TBM;
    const int bn = blockIdx.x * TBN;

    float acc[2][4][4];
#pragma unroll
    for (int mt = 0; mt < 2; mt++)
#pragma unroll
        for (int nt = 0; nt < 4; nt++)
#pragma unroll
            for (int i = 0; i < 4; i++) acc[mt][nt][i] = 0.f;

    for (int kt = 0; kt < K; kt += TBK) {
        // ---- A tile: 128 rows x 32 k; load fp32, BN/relu, split, pack ----
#pragma unroll
        for (int j = 0; j < 4; j++) {
            int v   = tid + 256 * j;       // 0..1023
            int row = v >> 3;              // 0..127
            int kq  = v & 7;               // float4 index along k
            int gr  = bm + row;
            int gk  = kt + kq * 4;
            float t[4] = {0.f, 0.f, 0.f, 0.f};
            if (gr < M && gk < K) {
                if (gk + 4 <= K) {
                    float4 q = *(const float4*)(A + (size_t)gr * K + gk);
                    t[0] = q.x; t[1] = q.y; t[2] = q.z; t[3] = q.w;
                } else {
#pragma unroll
                    for (int i = 0; i < 4; i++)
                        if (gk + i < K) t[i] = A[(size_t)gr * K + gk + i];
                }
                if (scaleA) {
#pragma unroll
                    for (int i = 0; i < 4; i++) {
                        if (gk + i < K) {
                            float u = fmaf(t[i], scaleA[gk + i], shiftA[gk + i]);
                            t[i] = reluA ? fmaxf(u, 0.f) : u;
                        }
                    }
                }
            }
            uint32_t h01, l01, h23, l23;
            split2(t[0], t[1], h01, l01);
            split2(t[2], t[3], h23, l23);
            Ah[row * AP_STR + kq * 2 + 0] = h01;
            Ah[row * AP_STR + kq * 2 + 1] = h23;
            Al[row * AP_STR + kq * 2 + 0] = l01;
            Al[row * AP_STR + kq * 2 + 1] = l23;
        }
        // ---- B tile: 32 k x 64 n; 256 threads = 16 kpairs x 16 n-quads ----
        {
            int kp = tid >> 4;             // 0..15
            int nq = tid & 15;             // 0..15
            int gk0 = kt + 2 * kp;
            int gn  = bn + nq * 4;
            float t0[4] = {0.f, 0.f, 0.f, 0.f};
            float t1[4] = {0.f, 0.f, 0.f, 0.f};
            if (gn < N) {                  // N % 4 == 0 always here
                if (gk0 < K) {
                    float4 q = *(const float4*)(B + (size_t)gk0 * N + gn);
                    t0[0] = q.x; t0[1] = q.y; t0[2] = q.z; t0[3] = q.w;
                }
                if (gk0 + 1 < K) {
                    float4 q = *(const float4*)(B + (size_t)(gk0 + 1) * N + gn);
                    t1[0] = q.x; t1[1] = q.y; t1[2] = q.z; t1[3] = q.w;
                }
            }
            uint32_t hw[4], lw[4];
#pragma unroll
            for (int i = 0; i < 4; i++) split2(t0[i], t1[i], hw[i], lw[i]);
            *(uint4*)&Bh[kp * BP_STR + nq * 4] = make_uint4(hw[0], hw[1], hw[2], hw[3]);
            *(uint4*)&Bl[kp * BP_STR + nq * 4] = make_uint4(lw[0], lw[1], lw[2], lw[3]);
        }
        __syncthreads();

        // ---- 2 k16 steps ----
#pragma unroll
        for (int ks = 0; ks < 2; ks++) {
            const int kpb = ks * 8;
            uint32_t ah[2][4], al[2][4];
#pragma unroll
            for (int mt = 0; mt < 2; mt++) {
                int m0 = wm * 32 + mt * 16;
                const uint32_t* p0 = Ah + (size_t)(m0 + r) * AP_STR + kpb + c;
                const uint32_t* p1 = Ah + (size_t)(m0 + r + 8) * AP_STR + kpb + c;
                ah[mt][0] = p0[0];
                ah[mt][1] = p1[0];
                ah[mt][2] = p0[4];
                ah[mt][3] = p1[4];
                const uint32_t* q0 = Al + (size_t)(m0 + r) * AP_STR + kpb + c;
                const uint32_t* q1 = Al + (size_t)(m0 + r + 8) * AP_STR + kpb + c;
                al[mt][0] = q0[0];
                al[mt][1] = q1[0];
                al[mt][2] = q0[4];
                al[mt][3] = q1[4];
            }
            uint32_t bh[4][2], bl[4][2];
#pragma unroll
            for (int nt = 0; nt < 4; nt++) {
                int col = wn * 32 + nt * 8 + r;
                bh[nt][0] = Bh[(size_t)(kpb + c) * BP_STR + col];
                bh[nt][1] = Bh[(size_t)(kpb + c + 4) * BP_STR + col];
                bl[nt][0] = Bl[(size_t)(kpb + c) * BP_STR + col];
                bl[nt][1] = Bl[(size_t)(kpb + c + 4) * BP_STR + col];
            }
#pragma unroll
            for (int mt = 0; mt < 2; mt++)
#pragma unroll
                for (int nt = 0; nt < 4; nt++) {
                    mma_bf16(acc[mt][nt], al[mt], bh[nt]);
                    mma_bf16(acc[mt][nt], ah[mt], bl[nt]);
                    mma_bf16(acc[mt][nt], ah[mt], bh[nt]);
                }
        }
        __syncthreads();
    }

    // ---- epilogue ----
#pragma unroll
    for (int mt = 0; mt < 2; mt++) {
        int row0 = bm + wm * 32 + mt * 16 + r;
#pragma unroll
        for (int nt = 0; nt < 4; nt++) {
            int col = bn + wn * 32 + nt * 8 + 2 * c;
            if (col >= N) continue;             // N even -> col+1 < N too
            float bx = bias[col], by = bias[col + 1];
            if (row0 < M) {
                float2 o = make_float2(acc[mt][nt][0] + bx, acc[mt][nt][1] + by);
                *(float2*)(C + (size_t)row0 * N + col) = o;
                if (C2) *(float2*)(C2 + (size_t)row0 * N + col) = o;
            }
            int row1 = row0 + 8;
            if (row1 < M) {
                float2 o = make_float2(acc[mt][nt][2] + bx, acc[mt][nt][3] + by);
                *(float2*)(C + (size_t)row1 * N + col) = o;
                if (C2) *(float2*)(C2 + (size_t)row1 * N + col) = o;
            }
        }
    }
}

// ---------------------------------------------------------------------------
// Edge encoder + message + scatter
// ---------------------------------------------------------------------------
#define EPB 128

__global__ __launch_bounds__(256)
void scatter_kernel(const float* __restrict__ edge_feat,
                    const int* __restrict__ src, const int* __restrict__ dst,
                    const float* __restrict__ eW, const float* __restrict__ eb,
                    const float* __restrict__ hn, float* __restrict__ acc, int E)
{
    __shared__ __align__(16) float Ws[EFEAT * DDIM];
    __shared__ __align__(16) float bs[DDIM];

    const int tid = threadIdx.x;
    for (int i = tid; i < EFEAT * DDIM; i += 256) Ws[i] = eW[i];
    for (int i = tid; i < DDIM; i += 256) bs[i] = eb[i];
    __syncthreads();

    const int warp = tid >> 5;
    const int lane = tid & 31;
    const int e0 = blockIdx.x * EPB + warp * (EPB / 8);
    const int e1 = min(e0 + (EPB / 8), E);

    for (int e = e0; e < e1; e++) {
        const int se = src[e];
        const int de = dst[e];
        const float4* ef4 = (const float4*)(edge_feat + (size_t)e * EFEAT);
        float efv[16];
#pragma unroll
        for (int i = 0; i < 4; i++) {
            float4 t = ef4[i];
            efv[4*i+0] = t.x; efv[4*i+1] = t.y; efv[4*i+2] = t.z; efv[4*i+3] = t.w;
        }
        const float* hrow = hn  + (size_t)se * DDIM;
        float*       arow = acc + (size_t)de * DDIM;

        for (int q = lane; q < DDIM / 4; q += 32) {
            const int d0 = q * 4;
            float4 h = *(const float4*)(bs + d0);
#pragma unroll
            for (int k = 0; k < 16; k++) {
                float ev = efv[k];
                float4 w = *(const float4*)(Ws + k * DDIM + d0);
                h.x = fmaf(ev, w.x, h.x);
                h.y = fmaf(ev, w.y, h.y);
                h.z = fmaf(ev, w.z, h.z);
                h.w = fmaf(ev, w.w, h.w);
            }
            float4 s = *(const float4*)(hrow + d0);
            float mx = fmaxf(s.x + h.x, 0.f);
            float my = fmaxf(s.y + h.y, 0.f);
            float mz = fmaxf(s.z + h.z, 0.f);
            float mw = fmaxf(s.w + h.w, 0.f);
            asm volatile("red.global.add.v4.f32 [%0], {%1,%2,%3,%4};"
                         :: "l"(arow + d0), "f"(mx), "f"(my), "f"(mz), "f"(mw)
                         : "memory");
        }
    }
}

// ---------------------------------------------------------------------------
// BatchNorm statistics (stat buffers are zero on entry; finalize re-zeros)
// ---------------------------------------------------------------------------
__global__ void colstats_kernel(const float* __restrict__ Y, int M, int Nc, int rowsPer)
{
    int c = threadIdx.x;
    if (c >= Nc) return;
    int r0 = blockIdx.x * rowsPer;
    int r1 = min(r0 + rowsPer, M);
    float s = 0.f, ss = 0.f;
    for (int r = r0; r < r1; r++) {
        float v = Y[(size_t)r * Nc + c];
        s += v;
        ss = fmaf(v, v, ss);
    }
    atomicAdd(&g_sum[c], s);
    atomicAdd(&g_sumsq[c], ss);
}

__global__ void finalize_kernel(const float* __restrict__ gamma,
                                const float* __restrict__ beta, int Nc, int M)
{
    int c = threadIdx.x + blockIdx.x * blockDim.x;
    if (c >= Nc) return;
    float s = g_sum[c], ss = g_sumsq[c];
    g_sum[c] = 0.f;                 // leave zeroed for the next use / replay
    g_sumsq[c] = 0.f;
    float invM = 1.f / (float)M;
    float mean = s * invM;
    float var  = fmaxf(ss * invM - mean * mean, 0.f);
    float sc   = gamma[c] * rsqrtf(var + BN_EPS);
    g_scale[c] = sc;
    g_shift[c] = beta[c] - mean * sc;
}

__global__ void apply_bn_kernel(const float* __restrict__ Y,
                                float* __restrict__ hn, float* __restrict__ accOut,
                                int relu, int total4)
{
    int i4 = threadIdx.x + blockIdx.x * blockDim.x;
    if (i4 >= total4) return;
    size_t idx = (size_t)i4 * 4;
    int d0 = (int)(idx % DDIM);
    float4 v = *(const float4*)(Y + idx);
    float4 o;
    o.x = fmaf(v.x, g_scale[d0+0], g_shift[d0+0]);
    o.y = fmaf(v.y, g_scale[d0+1], g_shift[d0+1]);
    o.z = fmaf(v.z, g_scale[d0+2], g_shift[d0+2]);
    o.w = fmaf(v.w, g_scale[d0+3], g_shift[d0+3]);
    if (relu) {
        o.x = fmaxf(o.x, 0.f); o.y = fmaxf(o.y, 0.f);
        o.z = fmaxf(o.z, 0.f); o.w = fmaxf(o.w, 0.f);
    }
    *(float4*)(hn + idx) = o;
    if (accOut) *(float4*)(accOut + idx) = o;
}

// ---------------------------------------------------------------------------
// Mean pooling + head
// ---------------------------------------------------------------------------
__device__ __forceinline__ int lower_bound_dev(const int* a, int n, int key)
{
    int lo = 0, hi = n;
    while (lo < hi) {
        int mid = (lo + hi) >> 1;
        if (a[mid] < key) lo = mid + 1; else hi = mid;
    }
    return lo;
}

__global__ void pool_kernel(const float* __restrict__ hn,
                            const int* __restrict__ gid, int Nn)
{
    __shared__ int s_lo, s_hi;
    int g = blockIdx.x;
    if (threadIdx.x == 0) {
        s_lo = lower_bound_dev(gid, Nn, g);
        s_hi = lower_bound_dev(gid, Nn, g + 1);
    }
    __syncthreads();
    int lo = s_lo, hi = s_hi;
    float inv = 1.f / fmaxf((float)(hi - lo), 1.f);
    for (int d = threadIdx.x; d < DDIM; d += blockDim.x) {
        float s = 0.f;
        for (int r = lo; r < hi; r++) s += hn[(size_t)r * DDIM + d];
        g_hg[g * DDIM + d] = s * inv;
    }
}

__global__ void pred_kernel(const float* __restrict__ W,
                            const float* __restrict__ b, float* __restrict__ out)
{
    __shared__ float h[DDIM];
    int g = blockIdx.x;
    for (int i = threadIdx.x; i < DDIM; i += blockDim.x) h[i] = g_hg[g * DDIM + i];
    __syncthreads();
    int o = threadIdx.x;
    float s = b[o];
    for (int k = 0; k < DDIM; k++)
        s = fmaf(h[k], W[k * OUTF + o], s);
    out[g * OUTF + o] = s;
}

// ---------------------------------------------------------------------------
// Launch
// ---------------------------------------------------------------------------
static inline int ceil_div(int a, int b) { return (a + b - 1) / b; }

extern "C" void kernel_launch(void* const* d_in, const int* in_sizes, int n_in,
                              void* d_out, int out_size)
{
    const float* node_feat = (const float*)d_in[0];
    const float* edge_feat = (const float*)d_in[1];
    const int*   src       = (const int*)d_in[2];
    const int*   dst       = (const int*)d_in[3];
    const int*   gid       = (const int*)d_in[4];

    int base = 5;
    if (in_sizes[5] == 1) base = 6;

    const float* node_W = (const float*)d_in[base + 0];
    const float* node_b = (const float*)d_in[base + 1];
    const float* edge_W = (const float*)d_in[base + 2];
    const float* edge_b = (const float*)d_in[base + 3];
    const float* W1     = (const float*)d_in[base + 4];
    const float* b1     = (const float*)d_in[base + 5];
    const float* g1     = (const float*)d_in[base + 6];
    const float* beta1  = (const float*)d_in[base + 7];
    const float* W2     = (const float*)d_in[base + 8];
    const float* b2     = (const float*)d_in[base + 9];
    const float* g2     = (const float*)d_in[base + 10];
    const float* beta2  = (const float*)d_in[base + 11];
    const float* pred_W = (const float*)d_in[base + 12];
    const float* pred_b = (const float*)d_in[base + 13];

    const int Nn = in_sizes[0] / NFEAT;
    const int E  = in_sizes[1] / EFEAT;

    float *hn, *acc, *y1, *y2, *scl, *shf;
    cudaGetSymbolAddress((void**)&hn,  g_hn);
    cudaGetSymbolAddress((void**)&acc, g_acc);
    cudaGetSymbolAddress((void**)&y1,  g_y1);
    cudaGetSymbolAddress((void**)&y2,  g_y2);
    cudaGetSymbolAddress((void**)&scl, g_scale);
    cudaGetSymbolAddress((void**)&shf, g_shift);

    // ---- node encoder ----
    {
        dim3 grid(ceil_div(DDIM, TBN), ceil_div(Nn, TBM));
        gemm_bf16x3_kernel<<<grid, 256>>>(node_feat, node_W, node_b,
                                          nullptr, nullptr, 0,
                                          hn, acc, Nn, DDIM, NFEAT);
    }

    const int statRows = 196;
    const int statGrid = ceil_div(Nn, statRows);

    for (int l = 0; l < LAYERS; l++) {
        scatter_kernel<<<ceil_div(E, EPB), 256>>>(
            edge_feat, src, dst,
            edge_W + (size_t)l * EFEAT * DDIM, edge_b + (size_t)l * DDIM,
            hn, acc, E);

        // Linear1
        {
            dim3 grid(ceil_div(DDIM2, TBN), ceil_div(Nn, TBM));
            gemm_bf16x3_kernel<<<grid, 256>>>(acc, W1 + (size_t)l * DDIM * DDIM2,
                                              b1 + (size_t)l * DDIM2,
                                              nullptr, nullptr, 0,
                                              y1, nullptr, Nn, DDIM2, DDIM);
        }
        colstats_kernel<<<statGrid, 640>>>(y1, Nn, DDIM2, statRows);
        finalize_kernel<<<1, DDIM2>>>(g1 + (size_t)l * DDIM2,
                                      beta1 + (size_t)l * DDIM2, DDIM2, Nn);

        // Linear2 with fused BN1 + relu on A
        {
            dim3 grid(ceil_div(DDIM, TBN), ceil_div(Nn, TBM));
            gemm_bf16x3_kernel<<<grid, 256>>>(y1, W2 + (size_t)l * DDIM2 * DDIM,
                                              b2 + (size_t)l * DDIM,
                                              scl, shf, 1,
                                              y2, nullptr, Nn, DDIM, DDIM2);
        }
        colstats_kernel<<<statGrid, 320>>>(y2, Nn, DDIM, statRows);
        finalize_kernel<<<1, DDIM>>>(g2 + (size_t)l * DDIM,
                                     beta2 + (size_t)l * DDIM, DDIM, Nn);

        {
            int total4 = Nn * DDIM / 4;
            int relu = (l != LAYERS - 1) ? 1 : 0;
            float* accOut = (l != LAYERS - 1) ? acc : nullptr;
            apply_bn_kernel<<<ceil_div(total4, 256), 256>>>(y2, hn, accOut,
                                                            relu, total4);
        }
    }

    pool_kernel<<<NGRAPH, 256>>>(hn, gid, Nn);
    pred_kernel<<<NGRAPH, OUTF>>>(pred_W, pred_b, (float*)d_out);
}

// round 6
// speedup vs baseline: 1.3499x; 1.3499x over previous
#include <cuda_runtime.h>
#include <cstdint>

// ---------------------------------------------------------------------------
// Problem constants
// ---------------------------------------------------------------------------
#define NFEAT   128
#define EFEAT   16
#define DDIM    300
#define DDIM2   600
#define LAYERS  3
#define NGRAPH  256
#define OUTF    128
#define BN_EPS  1e-5f

#define MAX_NODES 50000
#define MAX_EDGES 800000

// ---------------------------------------------------------------------------
// Scratch (device globals; no allocations allowed)
// ---------------------------------------------------------------------------
__device__ float g_hn [MAX_NODES * DDIM];
__device__ float g_acc[MAX_NODES * DDIM];
__device__ float g_y1 [MAX_NODES * DDIM2];
__device__ float g_y1b[MAX_NODES * DDIM2];   // relu(bn1(y1))
__device__ float g_y2 [MAX_NODES * DDIM];
__device__ float g_sum  [DDIM2];             // zero at entry; finalize re-zeros
__device__ float g_sumsq[DDIM2];
__device__ float g_scale[DDIM2];
__device__ float g_shift[DDIM2];
__device__ float g_hg [NGRAPH * DDIM];

// ---------------------------------------------------------------------------
// Split-TF32 (3xTF32) GEMM with cp.async double-buffered pipeline.
//   C = A @ B + bias ; optional fused per-column stats (sum / sumsq of C).
// Block tile 128x64x32, 8 warps (4x2), warp tile 32x32, m16n8k8 tf32 MMA.
// Compute section identical to the proven R4 kernel (rel_err 7.7e-6).
// ---------------------------------------------------------------------------
#define TBM 128
#define TBN 64
#define TBK 32
#define AS_STR 36
#define BS_STR 72
#define GEMM_SMEM_FLOATS (2 * TBM * AS_STR + 2 * TBK * BS_STR + 2 * TBN)
#define GEMM_SMEM_BYTES  (GEMM_SMEM_FLOATS * 4)

__device__ __forceinline__ void split_tf32(float x, uint32_t& hi, uint32_t& lo)
{
    uint32_t h;
    asm("cvt.rna.tf32.f32 %0, %1;" : "=r"(h) : "f"(x));
    float rem = x - __uint_as_float(h);
    uint32_t l;
    asm("cvt.rna.tf32.f32 %0, %1;" : "=r"(l) : "f"(rem));
    hi = h; lo = l;
}

__device__ __forceinline__ void mma_tf32(float acc[4], const uint32_t a[4],
                                         const uint32_t b[2])
{
    asm volatile(
        "mma.sync.aligned.m16n8k8.row.col.f32.tf32.tf32.f32 "
        "{%0,%1,%2,%3}, {%4,%5,%6,%7}, {%8,%9}, {%0,%1,%2,%3};"
        : "+f"(acc[0]), "+f"(acc[1]), "+f"(acc[2]), "+f"(acc[3])
        : "r"(a[0]), "r"(a[1]), "r"(a[2]), "r"(a[3]), "r"(b[0]), "r"(b[1]));
}

__device__ __forceinline__ void cp_async16(float* sdst, const float* gsrc, bool valid)
{
    uint32_t sa = (uint32_t)__cvta_generic_to_shared(sdst);
    int sz = valid ? 16 : 0;
    asm volatile("cp.async.cg.shared.global [%0], [%1], 16, %2;\n"
                 :: "r"(sa), "l"(gsrc), "r"(sz));
}

__global__ __launch_bounds__(256)
void gemm_tf32_pipe(const float* __restrict__ A, const float* __restrict__ B,
                    const float* __restrict__ bias,
                    float* __restrict__ C, float* __restrict__ C2, int doStats,
                    int M, int N, int K)
{
    extern __shared__ float smem[];
    float* AsBuf = smem;                              // 2 * TBM*AS_STR
    float* BsBuf = smem + 2 * TBM * AS_STR;           // 2 * TBK*BS_STR
    float* cstat = BsBuf + 2 * TBK * BS_STR;          // 2 * TBN

    const int tid  = threadIdx.x;
    const int warp = tid >> 5;
    const int lane = tid & 31;
    const int wm = warp >> 1;
    const int wn = warp & 1;
    const int r  = lane >> 2;
    const int c  = lane & 3;
    const int bm = blockIdx.y * TBM;
    const int bn = blockIdx.x * TBN;

    float acc[2][4][4];
#pragma unroll
    for (int mt = 0; mt < 2; mt++)
#pragma unroll
        for (int nt = 0; nt < 4; nt++)
#pragma unroll
            for (int i = 0; i < 4; i++) acc[mt][nt][i] = 0.f;

    const int T = (K + TBK - 1) / TBK;

    auto issue_tile = [&](int kt, int sel) {
        float* as = AsBuf + sel * (TBM * AS_STR);
        float* bs = BsBuf + sel * (TBK * BS_STR);
        // A: 128 rows x 32 k  (K % 4 == 0 always: 128 / 300 / 600)
#pragma unroll
        for (int j = 0; j < 4; j++) {
            int v   = tid + 256 * j;
            int row = v >> 3;
            int kq  = v & 7;
            int gr  = bm + row;
            int gk  = kt + kq * 4;
            bool val = (gr < M) && (gk < K);
            const float* srcp = val ? (A + (size_t)gr * K + gk) : A;
            cp_async16(as + row * AS_STR + kq * 4, srcp, val);
        }
        // B: 32 k x 64 n  (N % 4 == 0 always)
#pragma unroll
        for (int j = 0; j < 2; j++) {
            int v  = tid + 256 * j;
            int k  = v >> 4;
            int nq = v & 15;
            int gk = kt + k;
            int gn = bn + nq * 4;
            bool val = (gk < K) && (gn < N);
            const float* srcp = val ? (B + (size_t)gk * N + gn) : B;
            cp_async16(bs + k * BS_STR + nq * 4, srcp, val);
        }
        asm volatile("cp.async.commit_group;\n" ::: "memory");
    };

    issue_tile(0, 0);

    for (int t = 0; t < T; t++) {
        asm volatile("cp.async.wait_group 0;\n" ::: "memory");
        __syncthreads();
        if (t + 1 < T) issue_tile((t + 1) * TBK, (t + 1) & 1);

        const float* As = AsBuf + (t & 1) * (TBM * AS_STR);
        const float* Bs = BsBuf + (t & 1) * (TBK * BS_STR);

#pragma unroll
        for (int ks = 0; ks < 4; ks++) {
            uint32_t ah[2][4], al[2][4];
#pragma unroll
            for (int mt = 0; mt < 2; mt++) {
                int m0 = wm * 32 + mt * 16;
                const float* ap = As + (size_t)(m0 + r) * AS_STR + ks * 8 + c;
                split_tf32(ap[0],              ah[mt][0], al[mt][0]);
                split_tf32(ap[8 * AS_STR],     ah[mt][1], al[mt][1]);
                split_tf32(ap[4],              ah[mt][2], al[mt][2]);
                split_tf32(ap[8 * AS_STR + 4], ah[mt][3], al[mt][3]);
            }
            uint32_t bh[4][2], bl[4][2];
#pragma unroll
            for (int nt = 0; nt < 4; nt++) {
                int n0 = wn * 32 + nt * 8;
                const float* bp = Bs + (size_t)(ks * 8 + c) * BS_STR + n0 + r;
                split_tf32(bp[0],          bh[nt][0], bl[nt][0]);
                split_tf32(bp[4 * BS_STR], bh[nt][1], bl[nt][1]);
            }
#pragma unroll
            for (int mt = 0; mt < 2; mt++)
#pragma unroll
                for (int nt = 0; nt < 4; nt++) {
                    mma_tf32(acc[mt][nt], al[mt], bh[nt]);
                    mma_tf32(acc[mt][nt], ah[mt], bl[nt]);
                    mma_tf32(acc[mt][nt], ah[mt], bh[nt]);
                }
        }
        __syncthreads();
    }

    // ---- epilogue: bias + store + optional fused column stats ----
    float colS[8], colQ[8];
#pragma unroll
    for (int i = 0; i < 8; i++) { colS[i] = 0.f; colQ[i] = 0.f; }

#pragma unroll
    for (int mt = 0; mt < 2; mt++) {
        int row0 = bm + wm * 32 + mt * 16 + r;
#pragma unroll
        for (int nt = 0; nt < 4; nt++) {
            int col = bn + wn * 32 + nt * 8 + 2 * c;
            if (col >= N) continue;             // N even -> col+1 < N too
            float bx = bias[col], by = bias[col + 1];
            if (row0 < M) {
                float ox = acc[mt][nt][0] + bx;
                float oy = acc[mt][nt][1] + by;
                *(float2*)(C + (size_t)row0 * N + col) = make_float2(ox, oy);
                if (C2) *(float2*)(C2 + (size_t)row0 * N + col) = make_float2(ox, oy);
                colS[nt * 2 + 0] += ox; colQ[nt * 2 + 0] += ox * ox;
                colS[nt * 2 + 1] += oy; colQ[nt * 2 + 1] += oy * oy;
            }
            int row1 = row0 + 8;
            if (row1 < M) {
                float ox = acc[mt][nt][2] + bx;
                float oy = acc[mt][nt][3] + by;
                *(float2*)(C + (size_t)row1 * N + col) = make_float2(ox, oy);
                if (C2) *(float2*)(C2 + (size_t)row1 * N + col) = make_float2(ox, oy);
                colS[nt * 2 + 0] += ox; colQ[nt * 2 + 0] += ox * ox;
                colS[nt * 2 + 1] += oy; colQ[nt * 2 + 1] += oy * oy;
            }
        }
    }

    if (doStats) {
        if (tid < 2 * TBN) cstat[tid] = 0.f;
        __syncthreads();
#pragma unroll
        for (int nt = 0; nt < 4; nt++) {
#pragma unroll
            for (int p = 0; p < 2; p++) {
                int lc = wn * 32 + nt * 8 + 2 * c + p;
                if (bn + lc < N) {
                    atomicAdd(&cstat[lc],       colS[nt * 2 + p]);
                    atomicAdd(&cstat[TBN + lc], colQ[nt * 2 + p]);
                }
            }
        }
        __syncthreads();
        if (tid < TBN) {
            int gc = bn + tid;
            if (gc < N) {
                atomicAdd(&g_sum[gc],   cstat[tid]);
                atomicAdd(&g_sumsq[gc], cstat[TBN + tid]);
            }
        }
    }
}

// ---------------------------------------------------------------------------
// Edge encoder + message + scatter
// ---------------------------------------------------------------------------
#define EPB 128

__global__ __launch_bounds__(256)
void scatter_kernel(const float* __restrict__ edge_feat,
                    const int* __restrict__ src, const int* __restrict__ dst,
                    const float* __restrict__ eW, const float* __restrict__ eb,
                    const float* __restrict__ hn, float* __restrict__ acc, int E)
{
    __shared__ __align__(16) float Ws[EFEAT * DDIM];
    __shared__ __align__(16) float bs[DDIM];

    const int tid = threadIdx.x;
    for (int i = tid; i < EFEAT * DDIM; i += 256) Ws[i] = eW[i];
    for (int i = tid; i < DDIM; i += 256) bs[i] = eb[i];
    __syncthreads();

    const int warp = tid >> 5;
    const int lane = tid & 31;
    const int e0 = blockIdx.x * EPB + warp * (EPB / 8);
    const int e1 = min(e0 + (EPB / 8), E);

    for (int e = e0; e < e1; e++) {
        const int se = src[e];
        const int de = dst[e];
        const float4* ef4 = (const float4*)(edge_feat + (size_t)e * EFEAT);
        float efv[16];
#pragma unroll
        for (int i = 0; i < 4; i++) {
            float4 t = ef4[i];
            efv[4*i+0] = t.x; efv[4*i+1] = t.y; efv[4*i+2] = t.z; efv[4*i+3] = t.w;
        }
        const float* hrow = hn  + (size_t)se * DDIM;
        float*       arow = acc + (size_t)de * DDIM;

        for (int q = lane; q < DDIM / 4; q += 32) {
            const int d0 = q * 4;
            float4 h = *(const float4*)(bs + d0);
#pragma unroll
            for (int k = 0; k < 16; k++) {
                float ev = efv[k];
                float4 w = *(const float4*)(Ws + k * DDIM + d0);
                h.x = fmaf(ev, w.x, h.x);
                h.y = fmaf(ev, w.y, h.y);
                h.z = fmaf(ev, w.z, h.z);
                h.w = fmaf(ev, w.w, h.w);
            }
            float4 s = *(const float4*)(hrow + d0);
            float mx = fmaxf(s.x + h.x, 0.f);
            float my = fmaxf(s.y + h.y, 0.f);
            float mz = fmaxf(s.z + h.z, 0.f);
            float mw = fmaxf(s.w + h.w, 0.f);
            asm volatile("red.global.add.v4.f32 [%0], {%1,%2,%3,%4};"
                         :: "l"(arow + d0), "f"(mx), "f"(my), "f"(mz), "f"(mw)
                         : "memory");
        }
    }
}

// ---------------------------------------------------------------------------
// BN finalize (consumes + re-zeros stats) and BN apply
// ---------------------------------------------------------------------------
__global__ void finalize_kernel(const float* __restrict__ gamma,
                                const float* __restrict__ beta, int Nc, int M)
{
    int c = threadIdx.x + blockIdx.x * blockDim.x;
    if (c >= Nc) return;
    float s = g_sum[c], ss = g_sumsq[c];
    g_sum[c] = 0.f;                 // leave zeroed for next use / graph replay
    g_sumsq[c] = 0.f;
    float invM = 1.f / (float)M;
    float mean = s * invM;
    float var  = fmaxf(ss * invM - mean * mean, 0.f);
    float sc   = gamma[c] * rsqrtf(var + BN_EPS);
    g_scale[c] = sc;
    g_shift[c] = beta[c] - mean * sc;
}

__global__ void apply_bn_kernel(const float* __restrict__ Y,
                                float* __restrict__ out1, float* __restrict__ out2,
                                int relu, int total4, int Nc)
{
    int i4 = threadIdx.x + blockIdx.x * blockDim.x;
    if (i4 >= total4) return;
    size_t idx = (size_t)i4 * 4;
    int d0 = (int)(idx % Nc);                 // Nc % 4 == 0, no row crossing
    float4 v = *(const float4*)(Y + idx);
    float4 o;
    o.x = fmaf(v.x, g_scale[d0+0], g_shift[d0+0]);
    o.y = fmaf(v.y, g_scale[d0+1], g_shift[d0+1]);
    o.z = fmaf(v.z, g_scale[d0+2], g_shift[d0+2]);
    o.w = fmaf(v.w, g_scale[d0+3], g_shift[d0+3]);
    if (relu) {
        o.x = fmaxf(o.x, 0.f); o.y = fmaxf(o.y, 0.f);
        o.z = fmaxf(o.z, 0.f); o.w = fmaxf(o.w, 0.f);
    }
    *(float4*)(out1 + idx) = o;
    if (out2) *(float4*)(out2 + idx) = o;
}

// ---------------------------------------------------------------------------
// Mean pooling + head
// ---------------------------------------------------------------------------
__device__ __forceinline__ int lower_bound_dev(const int* a, int n, int key)
{
    int lo = 0, hi = n;
    while (lo < hi) {
        int mid = (lo + hi) >> 1;
        if (a[mid] < key) lo = mid + 1; else hi = mid;
    }
    return lo;
}

__global__ void pool_kernel(const float* __restrict__ hn,
                            const int* __restrict__ gid, int Nn)
{
    __shared__ int s_lo, s_hi;
    int g = blockIdx.x;
    if (threadIdx.x == 0) {
        s_lo = lower_bound_dev(gid, Nn, g);
        s_hi = lower_bound_dev(gid, Nn, g + 1);
    }
    __syncthreads();
    int lo = s_lo, hi = s_hi;
    float inv = 1.f / fmaxf((float)(hi - lo), 1.f);
    for (int d = threadIdx.x; d < DDIM; d += blockDim.x) {
        float s = 0.f;
        for (int r = lo; r < hi; r++) s += hn[(size_t)r * DDIM + d];
        g_hg[g * DDIM + d] = s * inv;
    }
}

__global__ void pred_kernel(const float* __restrict__ W,
                            const float* __restrict__ b, float* __restrict__ out)
{
    __shared__ float h[DDIM];
    int g = blockIdx.x;
    for (int i = threadIdx.x; i < DDIM; i += blockDim.x) h[i] = g_hg[g * DDIM + i];
    __syncthreads();
    int o = threadIdx.x;
    float s = b[o];
    for (int k = 0; k < DDIM; k++)
        s = fmaf(h[k], W[k * OUTF + o], s);
    out[g * OUTF + o] = s;
}

// ---------------------------------------------------------------------------
// Launch
// ---------------------------------------------------------------------------
static inline int ceil_div(int a, int b) { return (a + b - 1) / b; }

extern "C" void kernel_launch(void* const* d_in, const int* in_sizes, int n_in,
                              void* d_out, int out_size)
{
    const float* node_feat = (const float*)d_in[0];
    const float* edge_feat = (const float*)d_in[1];
    const int*   src       = (const int*)d_in[2];
    const int*   dst       = (const int*)d_in[3];
    const int*   gid       = (const int*)d_in[4];

    int base = 5;
    if (in_sizes[5] == 1) base = 6;

    const float* node_W = (const float*)d_in[base + 0];
    const float* node_b = (const float*)d_in[base + 1];
    const float* edge_W = (const float*)d_in[base + 2];
    const float* edge_b = (const float*)d_in[base + 3];
    const float* W1     = (const float*)d_in[base + 4];
    const float* b1     = (const float*)d_in[base + 5];
    const float* g1     = (const float*)d_in[base + 6];
    const float* beta1  = (const float*)d_in[base + 7];
    const float* W2     = (const float*)d_in[base + 8];
    const float* b2     = (const float*)d_in[base + 9];
    const float* g2     = (const float*)d_in[base + 10];
    const float* beta2  = (const float*)d_in[base + 11];
    const float* pred_W = (const float*)d_in[base + 12];
    const float* pred_b = (const float*)d_in[base + 13];

    const int Nn = in_sizes[0] / NFEAT;
    const int E  = in_sizes[1] / EFEAT;

    float *hn, *acc, *y1, *y1b, *y2;
    cudaGetSymbolAddress((void**)&hn,  g_hn);
    cudaGetSymbolAddress((void**)&acc, g_acc);
    cudaGetSymbolAddress((void**)&y1,  g_y1);
    cudaGetSymbolAddress((void**)&y1b, g_y1b);
    cudaGetSymbolAddress((void**)&y2,  g_y2);

    // 55.8 KB dynamic smem (first call happens outside graph capture)
    cudaFuncSetAttribute(gemm_tf32_pipe,
                         cudaFuncAttributeMaxDynamicSharedMemorySize,
                         GEMM_SMEM_BYTES);

    // ---- node encoder: hn = node_feat @ node_W + b ; acc = hn ----
    {
        dim3 grid(ceil_div(DDIM, TBN), ceil_div(Nn, TBM));
        gemm_tf32_pipe<<<grid, 256, GEMM_SMEM_BYTES>>>(
            node_feat, node_W, node_b, hn, acc, 0, Nn, DDIM, NFEAT);
    }

    for (int l = 0; l < LAYERS; l++) {
        scatter_kernel<<<ceil_div(E, EPB), 256>>>(
            edge_feat, src, dst,
            edge_W + (size_t)l * EFEAT * DDIM, edge_b + (size_t)l * DDIM,
            hn, acc, E);

        // Linear1 (stats fused into epilogue)
        {
            dim3 grid(ceil_div(DDIM2, TBN), ceil_div(Nn, TBM));
            gemm_tf32_pipe<<<grid, 256, GEMM_SMEM_BYTES>>>(
                acc, W1 + (size_t)l * DDIM * DDIM2, b1 + (size_t)l * DDIM2,
                y1, nullptr, 1, Nn, DDIM2, DDIM);
        }
        finalize_kernel<<<1, DDIM2>>>(g1 + (size_t)l * DDIM2,
                                      beta1 + (size_t)l * DDIM2, DDIM2, Nn);
        // y1b = relu(bn1(y1))
        {
            int total4 = Nn * DDIM2 / 4;
            apply_bn_kernel<<<ceil_div(total4, 256), 256>>>(y1, y1b, nullptr,
                                                            1, total4, DDIM2);
        }

        // Linear2 (stats fused into epilogue)  <- launch index 5 on layer 0
        {
            dim3 grid(ceil_div(DDIM, TBN), ceil_div(Nn, TBM));
            gemm_tf32_pipe<<<grid, 256, GEMM_SMEM_BYTES>>>(
                y1b, W2 + (size_t)l * DDIM2 * DDIM, b2 + (size_t)l * DDIM,
                y2, nullptr, 1, Nn, DDIM, DDIM2);
        }
        finalize_kernel<<<1, DDIM>>>(g2 + (size_t)l * DDIM,
                                     beta2 + (size_t)l * DDIM, DDIM, Nn);

        // hn = bn2(y2) (+relu except last); acc re-seeded for next layer
        {
            int total4 = Nn * DDIM / 4;
            int relu = (l != LAYERS - 1) ? 1 : 0;
            float* accOut = (l != LAYERS - 1) ? acc : nullptr;
            apply_bn_kernel<<<ceil_div(total4, 256), 256>>>(y2, hn, accOut,
                                                            relu, total4, DDIM);
        }
    }

    pool_kernel<<<NGRAPH, 256>>>(hn, gid, Nn);
    pred_kernel<<<NGRAPH, OUTF>>>(pred_W, pred_b, (float*)d_out);
}

// round 9
// speedup vs baseline: 1.6123x; 1.1944x over previous
#include <cuda_runtime.h>
#include <cuda_bf16.h>
#include <cstdint>

// ---------------------------------------------------------------------------
// Problem constants
// ---------------------------------------------------------------------------
#define NFEAT   128
#define EFEAT   16
#define DDIM    300
#define DDIM2   600
#define LAYERS  3
#define NGRAPH  256
#define OUTF    128
#define BN_EPS  1e-5f

#define MAX_NODES 50000
#define MAX_EDGES 800000

// Packed-plane strides (kp = k/2, padded to multiple of 16 for cp.async)
#define KPA_NODE 64     // K=128
#define KPA_ACC  160    // K=300 (Kp=150, pad->160)
#define KPA_Y1   304    // K=600 (Kp=300, pad->304)

// B-plane buffer layout (concatenated [kp][N] segments, uint32 words)
#define BOFF_NODE 0
#define BSZ_NODE  (64 * DDIM)                 // 19200
#define BOFF_W1   BSZ_NODE
#define BSZ_W1    (150 * DDIM2)               // 90000
#define BOFF_W2   (BOFF_W1 + LAYERS * BSZ_W1) // 289200
#define BSZ_W2    (300 * DDIM)                // 90000
#define BPL_TOTAL (BOFF_W2 + LAYERS * BSZ_W2) // 559200

// ---------------------------------------------------------------------------
// Scratch (device globals; no allocations allowed)
// ---------------------------------------------------------------------------
__device__ float g_hn [MAX_NODES * DDIM];
__device__ float g_acc[MAX_NODES * DDIM];
__device__ float g_y1 [MAX_NODES * DDIM2];
__device__ float g_y2 [MAX_NODES * DDIM];
__device__ float g_sum  [DDIM2];             // zero at entry; finalize re-zeros
__device__ float g_sumsq[DDIM2];
__device__ float g_scale[DDIM2];
__device__ float g_shift[DDIM2];
__device__ float g_hg [NGRAPH * DDIM];
__device__ uint32_t g_ahi[MAX_NODES * KPA_Y1];   // packed A hi plane (max K=600)
__device__ uint32_t g_alo[MAX_NODES * KPA_Y1];
__device__ uint32_t g_bhi[BPL_TOTAL];
__device__ uint32_t g_blo[BPL_TOTAL];

// ---------------------------------------------------------------------------
// bf16 split helpers (numerics validated in R5: rel_err 3.3e-5)
// ---------------------------------------------------------------------------
__device__ __forceinline__ uint32_t pack2(__nv_bfloat16 a, __nv_bfloat16 b)
{
    return ((uint32_t)__bfloat16_as_ushort(b) << 16) | __bfloat16_as_ushort(a);
}

__device__ __forceinline__ void split2(float x0, float x1,
                                       uint32_t& hi, uint32_t& lo)
{
    __nv_bfloat16 h0 = __float2bfloat16(x0);
    __nv_bfloat16 h1 = __float2bfloat16(x1);
    float r0 = x0 - __bfloat162float(h0);
    float r1 = x1 - __bfloat162float(h1);
    hi = pack2(h0, h1);
    lo = pack2(__float2bfloat16(r0), __float2bfloat16(r1));
}

__device__ __forceinline__ void mma_bf16(float acc[4], const uint32_t a[4],
                                         const uint32_t b[2])
{
    asm volatile(
        "mma.sync.aligned.m16n8k16.row.col.f32.bf16.bf16.f32 "
        "{%0,%1,%2,%3}, {%4,%5,%6,%7}, {%8,%9}, {%0,%1,%2,%3};"
        : "+f"(acc[0]), "+f"(acc[1]), "+f"(acc[2]), "+f"(acc[3])
        : "r"(a[0]), "r"(a[1]), "r"(a[2]), "r"(a[3]), "r"(b[0]), "r"(b[1]));
}

__device__ __forceinline__ void cp16(uint32_t* sdst, const uint32_t* gsrc, bool valid)
{
    uint32_t sa = (uint32_t)__cvta_generic_to_shared(sdst);
    int sz = valid ? 16 : 0;      // sz=0 -> 16B of zero-fill (validated R6)
    asm volatile("cp.async.cg.shared.global [%0], [%1], 16, %2;\n"
                 :: "r"(sa), "l"(gsrc), "r"(sz));
}

// ---------------------------------------------------------------------------
// Producer: split fp32 activations into packed hi/lo bf16 planes [M][KPA]
// (optional per-column BN affine + relu fused; pads kp >= K/2 with zeros)
// ---------------------------------------------------------------------------
__global__ void split_A_kernel(const float* __restrict__ X,
                               const float* __restrict__ scale,
                               const float* __restrict__ shift, int relu,
                               uint32_t* __restrict__ hi, uint32_t* __restrict__ lo,
                               int M, int K, int KPA)
{
    int i = blockIdx.x * blockDim.x + threadIdx.x;
    int total = M * KPA;
    if (i >= total) return;
    int row = i / KPA;
    int kp  = i - row * KPA;
    int k   = 2 * kp;
    uint32_t h = 0, l = 0;
    if (k < K) {                          // K even -> k+1 < K
        float2 v = *(const float2*)(X + (size_t)row * K + k);
        if (scale) {
            v.x = fmaf(v.x, scale[k],     shift[k]);
            v.y = fmaf(v.y, scale[k + 1], shift[k + 1]);
            if (relu) { v.x = fmaxf(v.x, 0.f); v.y = fmaxf(v.y, 0.f); }
        }
        split2(v.x, v.y, h, l);
    }
    hi[i] = h; lo[i] = l;
}

// ---------------------------------------------------------------------------
// Producer: split ALL weight matrices into packed planes [kp][N] (one launch)
// segments: node_W (64x300) | W1[0..2] (150x600) | W2[0..2] (300x300)
// ---------------------------------------------------------------------------
__global__ void split_W_kernel(const float* __restrict__ nodeW,
                               const float* __restrict__ W1,
                               const float* __restrict__ W2)
{
    int i = blockIdx.x * blockDim.x + threadIdx.x;
    if (i >= BPL_TOTAL) return;
    const float* src; int N, kp, n;
    if (i < BOFF_W1) {
        int t = i; kp = t / DDIM; n = t - kp * DDIM;
        src = nodeW; N = DDIM;
    } else if (i < BOFF_W2) {
        int j = i - BOFF_W1; int l = j / BSZ_W1; int t = j - l * BSZ_W1;
        kp = t / DDIM2; n = t - kp * DDIM2;
        src = W1 + (size_t)l * DDIM * DDIM2; N = DDIM2;
    } else {
        int j = i - BOFF_W2; int l = j / BSZ_W2; int t = j - l * BSZ_W2;
        kp = t / DDIM; n = t - kp * DDIM;
        src = W2 + (size_t)l * DDIM2 * DDIM; N = DDIM;
    }
    float f0 = src[(size_t)(2 * kp) * N + n];
    float f1 = src[(size_t)(2 * kp + 1) * N + n];
    uint32_t h, l2;
    split2(f0, f1, h, l2);
    g_bhi[i] = h; g_blo[i] = l2;
}

// ---------------------------------------------------------------------------
// bf16x3 GEMM on packed planes:  C = A @ B + bias  (+ optional column stats)
// Block 128x64, 8 warps (4x2), warp tile 32x32, m16n8k16 bf16 MMA.
// smem: A planes [128][20] u32 (conflict-free), B planes [16][72] u32,
// double-buffered cp.async. 48 MMA + 64 LDS per warp per 32-k tile; no ALU.
// ---------------------------------------------------------------------------
#define A_TILE_U32 (128 * 20)    // 2560
#define B_TILE_U32 (16 * 72)     // 1152
#define PK_SMEM_U32 (4 * A_TILE_U32 + 4 * B_TILE_U32 + 128)
#define PK_SMEM_BYTES (PK_SMEM_U32 * 4)      // 59904

__global__ __launch_bounds__(256)
void gemm_pk(const uint32_t* __restrict__ Ah, const uint32_t* __restrict__ Al,
             const uint32_t* __restrict__ Bh, const uint32_t* __restrict__ Bl,
             const float* __restrict__ bias,
             float* __restrict__ C, float* __restrict__ C2, int doStats,
             int M, int N, int Kp, int KPA)
{
    extern __shared__ uint32_t su[];
    uint32_t* AhS = su;                               // 2 buffers
    uint32_t* AlS = su + 2 * A_TILE_U32;
    uint32_t* BhS = su + 4 * A_TILE_U32;
    uint32_t* BlS = su + 4 * A_TILE_U32 + 2 * B_TILE_U32;
    float*  cstat = (float*)(su + 4 * A_TILE_U32 + 4 * B_TILE_U32);

    const int tid  = threadIdx.x;
    const int warp = tid >> 5;
    const int lane = tid & 31;
    const int wm = warp >> 1;
    const int wn = warp & 1;
    const int r  = lane >> 2;
    const int c  = lane & 3;
    const int bm = blockIdx.y * 128;
    const int bn = blockIdx.x * 64;

    float acc[2][4][4];
#pragma unroll
    for (int mt = 0; mt < 2; mt++)
#pragma unroll
        for (int nt = 0; nt < 4; nt++)
#pragma unroll
            for (int i = 0; i < 4; i++) acc[mt][nt][i] = 0.f;

    const int T = (Kp + 15) >> 4;

    auto issue_tile = [&](int t, int sel) {
        // A planes: 128 rows x 16 kp, hi+lo
#pragma unroll
        for (int j = 0; j < 4; j++) {
            int v   = tid + 256 * j;      // 0..1023
            int row = v >> 3;             // 0..127
            int q   = v & 7;
            int pl  = q >> 2;
            int qc  = q & 3;
            int kpo = t * 16 + qc * 4;
            bool val = (bm + row < M) && (kpo < KPA);   // KPA mult of 16
            const uint32_t* g = (pl ? Al : Ah);
            g = val ? (g + (size_t)(bm + row) * KPA + kpo) : g;
            uint32_t* s = (pl ? AlS : AhS) + sel * A_TILE_U32 + row * 20 + qc * 4;
            cp16(s, g, val);
        }
        // B planes: 16 kp rows x 64 n, hi+lo
#pragma unroll
        for (int j = 0; j < 2; j++) {
            int v  = tid + 256 * j;       // 0..511
            int pl = v >> 8;
            int w  = v & 255;
            int kr = w >> 4;
            int nc = w & 15;
            int kpo = t * 16 + kr;
            int gn  = bn + nc * 4;
            bool val = (kpo < Kp) && (gn < N);          // N mult of 4
            const uint32_t* g = (pl ? Bl : Bh);
            g = val ? (g + (size_t)kpo * N + gn) : g;
            uint32_t* s = (pl ? BlS : BhS) + sel * B_TILE_U32 + kr * 72 + nc * 4;
            cp16(s, g, val);
        }
        asm volatile("cp.async.commit_group;\n" ::: "memory");
    };

    issue_tile(0, 0);

    for (int t = 0; t < T; t++) {
        asm volatile("cp.async.wait_group 0;\n" ::: "memory");
        __syncthreads();
        if (t + 1 < T) issue_tile(t + 1, (t + 1) & 1);

        const int s = t & 1;
        const uint32_t* As_h = AhS + s * A_TILE_U32;
        const uint32_t* As_l = AlS + s * A_TILE_U32;
        const uint32_t* Bs_h = BhS + s * B_TILE_U32;
        const uint32_t* Bs_l = BlS + s * B_TILE_U32;

#pragma unroll
        for (int ks = 0; ks < 2; ks++) {
            const int kpb = ks * 8;
            uint32_t ah[2][4], al2[2][4];
#pragma unroll
            for (int mt = 0; mt < 2; mt++) {
                int m0 = wm * 32 + mt * 16;
                int o  = (m0 + r) * 20 + kpb + c;
                ah[mt][0]  = As_h[o];       ah[mt][1]  = As_h[o + 160];
                ah[mt][2]  = As_h[o + 4];   ah[mt][3]  = As_h[o + 164];
                al2[mt][0] = As_l[o];       al2[mt][1] = As_l[o + 160];
                al2[mt][2] = As_l[o + 4];   al2[mt][3] = As_l[o + 164];
            }
            uint32_t bh[4][2], bl2[4][2];
#pragma unroll
            for (int nt = 0; nt < 4; nt++) {
                int o = (kpb + c) * 72 + wn * 32 + nt * 8 + r;
                bh[nt][0]  = Bs_h[o];  bh[nt][1]  = Bs_h[o + 4 * 72];
                bl2[nt][0] = Bs_l[o];  bl2[nt][1] = Bs_l[o + 4 * 72];
            }
#pragma unroll
            for (int mt = 0; mt < 2; mt++)
#pragma unroll
                for (int nt = 0; nt < 4; nt++) {
                    mma_bf16(acc[mt][nt], al2[mt], bh[nt]);
                    mma_bf16(acc[mt][nt], ah[mt],  bl2[nt]);
                    mma_bf16(acc[mt][nt], ah[mt],  bh[nt]);
                }
        }
        __syncthreads();
    }

    // ---- epilogue: bias + store + optional fused column stats (R6-proven) ----
    float colS[8], colQ[8];
#pragma unroll
    for (int i = 0; i < 8; i++) { colS[i] = 0.f; colQ[i] = 0.f; }

#pragma unroll
    for (int mt = 0; mt < 2; mt++) {
        int row0 = bm + wm * 32 + mt * 16 + r;
#pragma unroll
        for (int nt = 0; nt < 4; nt++) {
            int col = bn + wn * 32 + nt * 8 + 2 * c;
            if (col >= N) continue;             // N even -> col+1 < N too
            float bx = bias[col], by = bias[col + 1];
            if (row0 < M) {
                float ox = acc[mt][nt][0] + bx;
                float oy = acc[mt][nt][1] + by;
                *(float2*)(C + (size_t)row0 * N + col) = make_float2(ox, oy);
                if (C2) *(float2*)(C2 + (size_t)row0 * N + col) = make_float2(ox, oy);
                colS[nt * 2 + 0] += ox; colQ[nt * 2 + 0] += ox * ox;
                colS[nt * 2 + 1] += oy; colQ[nt * 2 + 1] += oy * oy;
            }
            int row1 = row0 + 8;
            if (row1 < M) {
                float ox = acc[mt][nt][2] + bx;
                float oy = acc[mt][nt][3] + by;
                *(float2*)(C + (size_t)row1 * N + col) = make_float2(ox, oy);
                if (C2) *(float2*)(C2 + (size_t)row1 * N + col) = make_float2(ox, oy);
                colS[nt * 2 + 0] += ox; colQ[nt * 2 + 0] += ox * ox;
                colS[nt * 2 + 1] += oy; colQ[nt * 2 + 1] += oy * oy;
            }
        }
    }

    if (doStats) {
        if (tid < 128) cstat[tid] = 0.f;
        __syncthreads();
#pragma unroll
        for (int nt = 0; nt < 4; nt++) {
#pragma unroll
            for (int p = 0; p < 2; p++) {
                int lc = wn * 32 + nt * 8 + 2 * c + p;
                if (bn + lc < N) {
                    atomicAdd(&cstat[lc],      colS[nt * 2 + p]);
                    atomicAdd(&cstat[64 + lc], colQ[nt * 2 + p]);
                }
            }
        }
        __syncthreads();
        if (tid < 64) {
            int gc = bn + tid;
            if (gc < N) {
                atomicAdd(&g_sum[gc],   cstat[tid]);
                atomicAdd(&g_sumsq[gc], cstat[64 + tid]);
            }
        }
    }
}

// ---------------------------------------------------------------------------
// Edge encoder + message + scatter
// ---------------------------------------------------------------------------
#define EPB 128

__global__ __launch_bounds__(256)
void scatter_kernel(const float* __restrict__ edge_feat,
                    const int* __restrict__ src, const int* __restrict__ dst,
                    const float* __restrict__ eW, const float* __restrict__ eb,
                    const float* __restrict__ hn, float* __restrict__ acc, int E)
{
    __shared__ __align__(16) float Ws[EFEAT * DDIM];
    __shared__ __align__(16) float bs[DDIM];

    const int tid = threadIdx.x;
    for (int i = tid; i < EFEAT * DDIM; i += 256) Ws[i] = eW[i];
    for (int i = tid; i < DDIM; i += 256) bs[i] = eb[i];
    __syncthreads();

    const int warp = tid >> 5;
    const int lane = tid & 31;
    const int e0 = blockIdx.x * EPB + warp * (EPB / 8);
    const int e1 = min(e0 + (EPB / 8), E);

    for (int e = e0; e < e1; e++) {
        const int se = src[e];
        const int de = dst[e];
        const float4* ef4 = (const float4*)(edge_feat + (size_t)e * EFEAT);
        float efv[16];
#pragma unroll
        for (int i = 0; i < 4; i++) {
            float4 t = ef4[i];
            efv[4*i+0] = t.x; efv[4*i+1] = t.y; efv[4*i+2] = t.z; efv[4*i+3] = t.w;
        }
        const float* hrow = hn  + (size_t)se * DDIM;
        float*       arow = acc + (size_t)de * DDIM;

        for (int q = lane; q < DDIM / 4; q += 32) {
            const int d0 = q * 4;
            float4 h = *(const float4*)(bs + d0);
#pragma unroll
            for (int k = 0; k < 16; k++) {
                float ev = efv[k];
                float4 w = *(const float4*)(Ws + k * DDIM + d0);
                h.x = fmaf(ev, w.x, h.x);
                h.y = fmaf(ev, w.y, h.y);
                h.z = fmaf(ev, w.z, h.z);
                h.w = fmaf(ev, w.w, h.w);
            }
            float4 s = *(const float4*)(hrow + d0);
            float mx = fmaxf(s.x + h.x, 0.f);
            float my = fmaxf(s.y + h.y, 0.f);
            float mz = fmaxf(s.z + h.z, 0.f);
            float mw = fmaxf(s.w + h.w, 0.f);
            asm volatile("red.global.add.v4.f32 [%0], {%1,%2,%3,%4};"
                         :: "l"(arow + d0), "f"(mx), "f"(my), "f"(mz), "f"(mw)
                         : "memory");
        }
    }
}

// ---------------------------------------------------------------------------
// BN finalize (consumes + re-zeros stats) and BN apply
// ---------------------------------------------------------------------------
__global__ void finalize_kernel(const float* __restrict__ gamma,
                                const float* __restrict__ beta, int Nc, int M)
{
    int c = threadIdx.x + blockIdx.x * blockDim.x;
    if (c >= Nc) return;
    float s = g_sum[c], ss = g_sumsq[c];
    g_sum[c] = 0.f;
    g_sumsq[c] = 0.f;
    float invM = 1.f / (float)M;
    float mean = s * invM;
    float var  = fmaxf(ss * invM - mean * mean, 0.f);
    float sc   = gamma[c] * rsqrtf(var + BN_EPS);
    g_scale[c] = sc;
    g_shift[c] = beta[c] - mean * sc;
}

__global__ void apply_bn_kernel(const float* __restrict__ Y,
                                float* __restrict__ out1, float* __restrict__ out2,
                                int relu, int total4, int Nc)
{
    int i4 = threadIdx.x + blockIdx.x * blockDim.x;
    if (i4 >= total4) return;
    size_t idx = (size_t)i4 * 4;
    int d0 = (int)(idx % Nc);
    float4 v = *(const float4*)(Y + idx);
    float4 o;
    o.x = fmaf(v.x, g_scale[d0+0], g_shift[d0+0]);
    o.y = fmaf(v.y, g_scale[d0+1], g_shift[d0+1]);
    o.z = fmaf(v.z, g_scale[d0+2], g_shift[d0+2]);
    o.w = fmaf(v.w, g_scale[d0+3], g_shift[d0+3]);
    if (relu) {
        o.x = fmaxf(o.x, 0.f); o.y = fmaxf(o.y, 0.f);
        o.z = fmaxf(o.z, 0.f); o.w = fmaxf(o.w, 0.f);
    }
    *(float4*)(out1 + idx) = o;
    if (out2) *(float4*)(out2 + idx) = o;
}

// ---------------------------------------------------------------------------
// Mean pooling + head
// ---------------------------------------------------------------------------
__device__ __forceinline__ int lower_bound_dev(const int* a, int n, int key)
{
    int lo = 0, hi = n;
    while (lo < hi) {
        int mid = (lo + hi) >> 1;
        if (a[mid] < key) lo = mid + 1; else hi = mid;
    }
    return lo;
}

__global__ void pool_kernel(const float* __restrict__ hn,
                            const int* __restrict__ gid, int Nn)
{
    __shared__ int s_lo, s_hi;
    int g = blockIdx.x;
    if (threadIdx.x == 0) {
        s_lo = lower_bound_dev(gid, Nn, g);
        s_hi = lower_bound_dev(gid, Nn, g + 1);
    }
    __syncthreads();
    int lo = s_lo, hi = s_hi;
    float inv = 1.f / fmaxf((float)(hi - lo), 1.f);
    for (int d = threadIdx.x; d < DDIM; d += blockDim.x) {
        float s = 0.f;
        for (int r = lo; r < hi; r++) s += hn[(size_t)r * DDIM + d];
        g_hg[g * DDIM + d] = s * inv;
    }
}

__global__ void pred_kernel(const float* __restrict__ W,
                            const float* __restrict__ b, float* __restrict__ out)
{
    __shared__ float h[DDIM];
    int g = blockIdx.x;
    for (int i = threadIdx.x; i < DDIM; i += blockDim.x) h[i] = g_hg[g * DDIM + i];
    __syncthreads();
    int o = threadIdx.x;
    float s = b[o];
    for (int k = 0; k < DDIM; k++)
        s = fmaf(h[k], W[k * OUTF + o], s);
    out[g * OUTF + o] = s;
}

// ---------------------------------------------------------------------------
// Launch
// ---------------------------------------------------------------------------
static inline int ceil_div(int a, int b) { return (a + b - 1) / b; }

extern "C" void kernel_launch(void* const* d_in, const int* in_sizes, int n_in,
                              void* d_out, int out_size)
{
    const float* node_feat = (const float*)d_in[0];
    const float* edge_feat = (const float*)d_in[1];
    const int*   src       = (const int*)d_in[2];
    const int*   dst       = (const int*)d_in[3];
    const int*   gid       = (const int*)d_in[4];

    int base = 5;
    if (in_sizes[5] == 1) base = 6;

    const float* node_W = (const float*)d_in[base + 0];
    const float* node_b = (const float*)d_in[base + 1];
    const float* edge_W = (const float*)d_in[base + 2];
    const float* edge_b = (const float*)d_in[base + 3];
    const float* W1     = (const float*)d_in[base + 4];
    const float* b1     = (const float*)d_in[base + 5];
    const float* g1     = (const float*)d_in[base + 6];
    const float* beta1  = (const float*)d_in[base + 7];
    const float* W2     = (const float*)d_in[base + 8];
    const float* b2     = (const float*)d_in[base + 9];
    const float* g2     = (const float*)d_in[base + 10];
    const float* beta2  = (const float*)d_in[base + 11];
    const float* pred_W = (const float*)d_in[base + 12];
    const float* pred_b = (const float*)d_in[base + 13];

    const int Nn = in_sizes[0] / NFEAT;
    const int E  = in_sizes[1] / EFEAT;

    float *hn, *acc, *y1, *y2, *scl, *shf;
    uint32_t *ahi, *alo, *bhi, *blo;
    cudaGetSymbolAddress((void**)&hn,  g_hn);
    cudaGetSymbolAddress((void**)&acc, g_acc);
    cudaGetSymbolAddress((void**)&y1,  g_y1);
    cudaGetSymbolAddress((void**)&y2,  g_y2);
    cudaGetSymbolAddress((void**)&scl, g_scale);
    cudaGetSymbolAddress((void**)&shf, g_shift);
    cudaGetSymbolAddress((void**)&ahi, g_ahi);
    cudaGetSymbolAddress((void**)&alo, g_alo);
    cudaGetSymbolAddress((void**)&bhi, g_bhi);
    cudaGetSymbolAddress((void**)&blo, g_blo);

    cudaFuncSetAttribute(gemm_pk,
                         cudaFuncAttributeMaxDynamicSharedMemorySize,
                         PK_SMEM_BYTES);

    // launch 0: split all weight matrices into packed planes
    split_W_kernel<<<ceil_div(BPL_TOTAL, 256), 256>>>(node_W, W1, W2);

    // launch 1: split node_feat
    split_A_kernel<<<ceil_div(Nn * KPA_NODE, 256), 256>>>(
        node_feat, nullptr, nullptr, 0, ahi, alo, Nn, NFEAT, KPA_NODE);

    // launch 2: node encoder GEMM -> hn (and acc)
    {
        dim3 grid(ceil_div(DDIM, 64), ceil_div(Nn, 128));
        gemm_pk<<<grid, 256, PK_SMEM_BYTES>>>(
            ahi, alo, bhi + BOFF_NODE, blo + BOFF_NODE, node_b,
            hn, acc, 0, Nn, DDIM, 64, KPA_NODE);
    }

    for (int l = 0; l < LAYERS; l++) {
        // scatter (launch 3 on l=0)
        scatter_kernel<<<ceil_div(E, EPB), 256>>>(
            edge_feat, src, dst,
            edge_W + (size_t)l * EFEAT * DDIM, edge_b + (size_t)l * DDIM,
            hn, acc, E);

        // launch 4: split acc
        split_A_kernel<<<ceil_div(Nn * KPA_ACC, 256), 256>>>(
            acc, nullptr, nullptr, 0, ahi, alo, Nn, DDIM, KPA_ACC);

        // launch 5 (l=0): Linear1 GEMM y1 = acc @ W1 + b1, stats fused
        {
            dim3 grid(ceil_div(DDIM2, 64), ceil_div(Nn, 128));
            gemm_pk<<<grid, 256, PK_SMEM_BYTES>>>(
                ahi, alo, bhi + BOFF_W1 + l * BSZ_W1, blo + BOFF_W1 + l * BSZ_W1,
                b1 + (size_t)l * DDIM2, y1, nullptr, 1, Nn, DDIM2, 150, KPA_ACC);
        }
        finalize_kernel<<<1, DDIM2>>>(g1 + (size_t)l * DDIM2,
                                      beta1 + (size_t)l * DDIM2, DDIM2, Nn);

        // split y1 with fused BN1 + relu
        split_A_kernel<<<ceil_div(Nn * KPA_Y1, 256), 256>>>(
            y1, scl, shf, 1, ahi, alo, Nn, DDIM2, KPA_Y1);

        // Linear2 GEMM y2 = relu(bn1(y1)) @ W2 + b2, stats fused
        {
            dim3 grid(ceil_div(DDIM, 64), ceil_div(Nn, 128));
            gemm_pk<<<grid, 256, PK_SMEM_BYTES>>>(
                ahi, alo, bhi + BOFF_W2 + l * BSZ_W2, blo + BOFF_W2 + l * BSZ_W2,
                b2 + (size_t)l * DDIM, y2, nullptr, 1, Nn, DDIM, 300, KPA_Y1);
        }
        finalize_kernel<<<1, DDIM>>>(g2 + (size_t)l * DDIM,
                                     beta2 + (size_t)l * DDIM, DDIM, Nn);

        // hn = bn2(y2) (+relu except last); acc re-seeded for next layer
        {
            int total4 = Nn * DDIM / 4;
            int relu = (l != LAYERS - 1) ? 1 : 0;
            float* accOut = (l != LAYERS - 1) ? acc : nullptr;
            apply_bn_kernel<<<ceil_div(total4, 256), 256>>>(y2, hn, accOut,
                                                            relu, total4, DDIM);
        }
    }

    pool_kernel<<<NGRAPH, 256>>>(hn, gid, Nn);
    pred_kernel<<<NGRAPH, OUTF>>>(pred_W, pred_b, (float*)d_out);
}